// round 13
// baseline (speedup 1.0000x reference)
#include <cuda_runtime.h>
#include <cstdint>

// ---------------------------------------------------------------------------
// self_attention: B=2, S=2048, D=1024, H=16, HD=64, fp32.
// Stage 0: maskpack: int32 mask [B,S,S] -> bitmask (1 MB)
// Stage 1: qh/kh/vh = {q,k,v} @ {wq,wk,wv}  -> [B,H,S,HD]  (one launch, z=3)
// Stage 2: FUSED attention (validated R12, 858.6us pipeline) — unchanged.
// Stage 3: out = ao @ wo + bo
// GEMM core: mma.sync.m16n8k16 BF16 "bf16x3" (validated rel_err 2.2e-5).
// R13: proj/out GEMMs use PRE-SPLIT packed bf16 hi/lo SMEM — loaders convert
// once (LDG->split2->STS), consumers do pure LDS.64 + HMMA (no per-warp
// redundant conversion; was 3x redundant, alu=24.3% -> ~10%).
// ---------------------------------------------------------------------------

namespace cfg {
constexpr int kS  = 2048;
constexpr int kD  = 1024;
constexpr int kH  = 16;
constexpr int kHD = 64;
constexpr int kB  = 2;
constexpr int kM  = kB * kS;   // 4096
constexpr int kBH = kB * kH;   // 32
constexpr int kW  = kS / 32;   // 64 mask words per row
}
using namespace cfg;

__device__ float g_qh[kBH * kS * kHD];                       // 16 MB
__device__ float g_kh[kBH * kS * kHD];                       // 16 MB
__device__ float g_vh[kBH * kS * kHD];                       // 16 MB
__device__ float g_ao[(size_t)kM * kD];                      // 16 MB
__device__ uint32_t g_mb[kB * kS * kW];                      // 1 MB bitmask

// ---------------------------------------------------------------------------
// async-copy + bf16 helpers (validated R8/R12)
// ---------------------------------------------------------------------------
__device__ __forceinline__ uint32_t smem_u32(const void* p)
{
    return (uint32_t)__cvta_generic_to_shared(p);
}
__device__ __forceinline__ void cp16(uint32_t dst, const void* src)
{
    asm volatile("cp.async.cg.shared.global [%0], [%1], 16;" ::
                 "r"(dst), "l"(src));
}
__device__ __forceinline__ void cp_commit()
{
    asm volatile("cp.async.commit_group;");
}
__device__ __forceinline__ void cp_wait0()
{
    asm volatile("cp.async.wait_group 0;");
}
__device__ __forceinline__ uint32_t pack_bf16(float x0, float x1)
{
    uint32_t r;
    asm("cvt.rn.bf16x2.f32 %0, %1, %2;" : "=r"(r) : "f"(x1), "f"(x0));
    return r;
}
__device__ __forceinline__ void split2(float x0, float x1,
                                       uint32_t& h, uint32_t& l)
{
    h = pack_bf16(x0, x1);
    const float h0 = __uint_as_float(h << 16);
    const float h1 = __uint_as_float(h & 0xFFFF0000u);
    l = pack_bf16(x0 - h0, x1 - h1);
}
__device__ __forceinline__ void mma_bf16(float d[4], const uint32_t a[4],
                                         const uint32_t b[2])
{
    asm volatile(
        "mma.sync.aligned.m16n8k16.row.col.f32.bf16.bf16.f32 "
        "{%0,%1,%2,%3}, {%4,%5,%6,%7}, {%8,%9}, {%0,%1,%2,%3};"
        : "+f"(d[0]), "+f"(d[1]), "+f"(d[2]), "+f"(d[3])
        : "r"(a[0]), "r"(a[1]), "r"(a[2]), "r"(a[3]), "r"(b[0]), "r"(b[1]));
}

// ---------------------------------------------------------------------------
// Packed-SMEM warp-tile MMA over one BK=16 slab.
// Asp [m][LDAW] uint32: [m][2*k2]=hi(k=2k2,2k2+1), [2*k2+1]=lo.
// Bsp [k2][LDBW] uint32: [k2][2*c]=hi(B[2k2][c],B[2k2+1][c]), [2*c+1]=lo.
// Fragment = one LDS.64 (hi,lo); zero conversion ALU in the consumer.
// ---------------------------------------------------------------------------
template <int MT, int NT, int LDAW, int LDBW>
__device__ __forceinline__ void warp_mma_packed(
    const uint32_t (*Asp)[LDAW], const uint32_t (*Bsp)[LDBW],
    float acc[MT][NT][4], int mbase, int nbase, int g, int t)
{
    uint32_t ah[MT][4], al[MT][4];
#pragma unroll
    for (int mt = 0; mt < MT; mt++) {
        const int r0 = mbase + mt * 16 + g;
        uint2 w0 = *(const uint2*)&Asp[r0][2 * t];
        uint2 w1 = *(const uint2*)&Asp[r0 + 8][2 * t];
        uint2 w2 = *(const uint2*)&Asp[r0][2 * t + 8];
        uint2 w3 = *(const uint2*)&Asp[r0 + 8][2 * t + 8];
        ah[mt][0] = w0.x; al[mt][0] = w0.y;
        ah[mt][1] = w1.x; al[mt][1] = w1.y;
        ah[mt][2] = w2.x; al[mt][2] = w2.y;
        ah[mt][3] = w3.x; al[mt][3] = w3.y;
    }
    uint32_t bh[NT][2], bl[NT][2];
#pragma unroll
    for (int nt = 0; nt < NT; nt++) {
        const int c = nbase + nt * 8 + g;
        uint2 w0 = *(const uint2*)&Bsp[t][2 * c];
        uint2 w1 = *(const uint2*)&Bsp[t + 4][2 * c];
        bh[nt][0] = w0.x; bl[nt][0] = w0.y;
        bh[nt][1] = w1.x; bl[nt][1] = w1.y;
    }
#pragma unroll
    for (int mt = 0; mt < MT; mt++)
#pragma unroll
        for (int nt = 0; nt < NT; nt++) {
            mma_bf16(acc[mt][nt], ah[mt], bh[nt]);
            mma_bf16(acc[mt][nt], ah[mt], bl[nt]);
            mma_bf16(acc[mt][nt], al[mt], bh[nt]);
        }
}

// ---------------------------------------------------------------------------
// Stage 1 & 3 shared body: C[128,128] tile of A[M,kD] @ W[kD,kD].
// Packed hi/lo SMEM; loaders LDG->split2->STS once per element.
// EPI: 0 = [B,H,S,HD] remap (proj), 1 = row-major + bias (out).
// ---------------------------------------------------------------------------
template <int EPI>
__device__ __forceinline__ void gemm_d_body(
    const float* __restrict__ A, const float* __restrict__ W,
    const float* __restrict__ bias, float* __restrict__ out)
{
    __shared__ __align__(16) uint32_t As[2][128][24];   // 24.0 KB
    __shared__ __align__(16) uint32_t Bs[2][8][264];    // 16.5 KB
    const int tid = threadIdx.x;
    const int warp = tid >> 5, lane = tid & 31;
    const int g = lane >> 2, t = lane & 3;
    const int wm = warp & 1, wn = warp >> 1;       // 2 x 4 warp grid
    const int m0 = blockIdx.x * 128;
    const int n0 = blockIdx.y * 128;
    const int ar = tid >> 2, ac = (tid & 3) * 4;   // A: rows ar, ar+64; k ac..ac+3
    const int bp = tid >> 5, bc = (tid & 31) * 4;  // B: k-pair bp, cols bc..bc+3

    const float* aSrc0 = &A[(size_t)(m0 + ar) * kD + ac];
    const float* aSrc1 = &A[(size_t)(m0 + ar + 64) * kD + ac];
    const float* bSrc0 = &W[(size_t)(2 * bp) * kD + n0 + bc];
    const float* bSrc1 = bSrc0 + kD;               // row 2*bp+1

    float4 pa0, pa1, pb0, pb1;
    // prologue: slab 0 -> regs
    pa0 = *(const float4*)aSrc0;
    pa1 = *(const float4*)aSrc1;
    pb0 = *(const float4*)bSrc0;
    pb1 = *(const float4*)bSrc1;

    // convert + store helper (A pairs along k in-row; B pairs across k-rows)
    auto store_slab = [&](int buf, const float4& a0, const float4& a1,
                          const float4& b0, const float4& b1) {
        uint32_t h0, l0, h1, l1;
        split2(a0.x, a0.y, h0, l0);
        split2(a0.z, a0.w, h1, l1);
        *(uint4*)&As[buf][ar][ac] = make_uint4(h0, l0, h1, l1);
        split2(a1.x, a1.y, h0, l0);
        split2(a1.z, a1.w, h1, l1);
        *(uint4*)&As[buf][ar + 64][ac] = make_uint4(h0, l0, h1, l1);
        uint32_t bh0, bl0, bh1, bl1, bh2, bl2, bh3, bl3;
        split2(b0.x, b1.x, bh0, bl0);
        split2(b0.y, b1.y, bh1, bl1);
        split2(b0.z, b1.z, bh2, bl2);
        split2(b0.w, b1.w, bh3, bl3);
        *(uint4*)&Bs[buf][bp][2 * bc]     = make_uint4(bh0, bl0, bh1, bl1);
        *(uint4*)&Bs[buf][bp][2 * bc + 4] = make_uint4(bh2, bl2, bh3, bl3);
    };

    store_slab(0, pa0, pa1, pb0, pb1);
    __syncthreads();

    float acc[4][4][4] = {};
    constexpr int NS = kD / 16;
    for (int s = 0; s < NS; s++) {
        const int cur = s & 1, nxt = cur ^ 1;
        const bool more = (s + 1 < NS);
        if (more) {
            const int k0 = (s + 1) * 16;
            pa0 = *(const float4*)(aSrc0 + k0);
            pa1 = *(const float4*)(aSrc1 + k0);
            pb0 = *(const float4*)(bSrc0 + (size_t)k0 * kD);
            pb1 = *(const float4*)(bSrc1 + (size_t)k0 * kD);
        }
        warp_mma_packed<4, 4, 24, 264>(As[cur], Bs[cur], acc,
                                       wm * 64, wn * 32, g, t);
        if (more) {
            store_slab(nxt, pa0, pa1, pb0, pb1);
            __syncthreads();
        }
    }

#pragma unroll
    for (int mt = 0; mt < 4; mt++) {
#pragma unroll
        for (int nt = 0; nt < 4; nt++) {
            const int r0 = m0 + wm * 64 + mt * 16 + g;
            const int r1 = r0 + 8;
            const int c  = n0 + wn * 32 + nt * 8 + 2 * t;
            const float* d = acc[mt][nt];
            if (EPI == 0) {
                const int h = c >> 6, dd = c & 63;
                const int bb0 = r0 >> 11, ss0 = r0 & (kS - 1);
                const int bb1 = r1 >> 11, ss1 = r1 & (kS - 1);
                *(float2*)&out[((size_t)(bb0 * kH + h) * kS + ss0) * kHD + dd] =
                    make_float2(d[0], d[1]);
                *(float2*)&out[((size_t)(bb1 * kH + h) * kS + ss1) * kHD + dd] =
                    make_float2(d[2], d[3]);
            } else {
                const float2 bv = *(const float2*)&bias[c];
                *(float2*)&out[(size_t)r0 * kD + c] =
                    make_float2(d[0] + bv.x, d[1] + bv.y);
                *(float2*)&out[(size_t)r1 * kD + c] =
                    make_float2(d[2] + bv.x, d[3] + bv.y);
            }
        }
    }
}

__global__ __launch_bounds__(256) void proj_kernel(
    const float* __restrict__ q, const float* __restrict__ k,
    const float* __restrict__ v, const float* __restrict__ wq,
    const float* __restrict__ wk, const float* __restrict__ wv)
{
    const int which = blockIdx.z;
    const float* A = (which == 0) ? q : ((which == 1) ? k : v);
    const float* W = (which == 0) ? wq : ((which == 1) ? wk : wv);
    float* out = (which == 0) ? g_qh : ((which == 1) ? g_kh : g_vh);
    gemm_d_body<0>(A, W, nullptr, out);
}

__global__ __launch_bounds__(256) void out_kernel(
    const float* __restrict__ W, const float* __restrict__ bias,
    float* __restrict__ out)
{
    gemm_d_body<1>(g_ao, W, bias, out);
}

// ---------------------------------------------------------------------------
// Stage 0: pack mask ints into bits. One warp packs 32 words (coalesced).
// ---------------------------------------------------------------------------
__global__ __launch_bounds__(256) void maskpack_kernel(const int* __restrict__ mask)
{
    const int warp = threadIdx.x >> 5, lane = threadIdx.x & 31;
    const int wbase = (blockIdx.x * 8 + warp) * 32;
#pragma unroll 4
    for (int i = 0; i < 32; i++) {
        const int w = wbase + i;
        const int v = mask[(size_t)w * 32 + lane];
        const uint32_t b = __ballot_sync(0xffffffffu, v != 0);
        if (lane == 0) g_mb[w] = b;
    }
}

// ---------------------------------------------------------------------------
// Stage 2: fused attention (UNCHANGED from R12 passing version).
// ---------------------------------------------------------------------------
__global__ __launch_bounds__(256) void attn_kernel()
{
    __shared__ __align__(16) char sm[35840];
    float* KsBase = (float*)sm;              // 2 x 64 x 36 floats (18432 B)
    float* VsBase = (float*)(sm + 18432);    // 2 x 32 x 68 floats (17408 B)
    float* Qs     = (float*)sm;              // 128 x 68 staging (34816 B)

    const int tid = threadIdx.x;
    const int warp = tid >> 5, lane = tid & 31;
    const int g = lane >> 2, t = lane & 3;
    const int q0 = blockIdx.x * 128;
    const int bh = blockIdx.y;
    const int bb = bh >> 4, h = bh & 15;
    const float* Qp = g_qh + (size_t)bh * kS * kHD;
    const float* Kp = g_kh + (size_t)bh * kS * kHD;
    const float* Vp = g_vh + (size_t)bh * kS * kHD;

    // ---- stage Q (128x64) into Qs, then extract per-warp A-fragments ----
    {
        const int r = tid >> 1;
        const int cb = (tid & 1) * 32;
        const float* src = Qp + (size_t)(q0 + r) * kHD + cb;
        const uint32_t dst = smem_u32(&Qs[r * 68 + cb]);
#pragma unroll
        for (int j = 0; j < 8; j++)
            cp16(dst + j * 16, src + j * 4);
        cp_commit();
        cp_wait0();
    }
    __syncthreads();

    uint32_t qa_h[4][4], qa_l[4][4];
    {
        const int r0 = warp * 16 + g;
#pragma unroll
        for (int j = 0; j < 4; j++) {
            const float2 x0 = *(const float2*)&Qs[r0 * 68 + 16 * j + 2 * t];
            const float2 x1 = *(const float2*)&Qs[(r0 + 8) * 68 + 16 * j + 2 * t];
            const float2 x2 = *(const float2*)&Qs[r0 * 68 + 16 * j + 2 * t + 8];
            const float2 x3 = *(const float2*)&Qs[(r0 + 8) * 68 + 16 * j + 2 * t + 8];
            split2(x0.x, x0.y, qa_h[j][0], qa_l[j][0]);
            split2(x1.x, x1.y, qa_h[j][1], qa_l[j][1]);
            split2(x2.x, x2.y, qa_h[j][2], qa_l[j][2]);
            split2(x3.x, x3.y, qa_h[j][3], qa_l[j][3]);
        }
    }
    __syncthreads();   // Qs region now free for Ks/Vs

    const int kband = warp * 8;
    const int vkey = tid >> 3;
    const int vhd  = (tid & 7) * 8;

    // chunk 0 -> buffer 0
    {
        const float* ks = Kp + (size_t)lane * kHD + kband;
        const float4 k0 = *(const float4*)ks;
        const float4 k1 = *(const float4*)(ks + 4);
        float* K0 = KsBase;
        K0[(kband + 0) * 36 + lane] = k0.x;
        K0[(kband + 1) * 36 + lane] = k0.y;
        K0[(kband + 2) * 36 + lane] = k0.z;
        K0[(kband + 3) * 36 + lane] = k0.w;
        K0[(kband + 4) * 36 + lane] = k1.x;
        K0[(kband + 5) * 36 + lane] = k1.y;
        K0[(kband + 6) * 36 + lane] = k1.z;
        K0[(kband + 7) * 36 + lane] = k1.w;
        const uint32_t vdst = smem_u32(VsBase + vkey * 68 + vhd);
        const float* vs = Vp + (size_t)vkey * kHD + vhd;
        cp16(vdst, vs);
        cp16(vdst + 16, vs + 4);
        cp_commit();
        cp_wait0();
    }
    __syncthreads();

    float oacc[8][4] = {};
    float rs0 = 0.0f, rs1 = 0.0f;
    const int qrow0 = q0 + warp * 16 + g;
    const int qrow1 = qrow0 + 8;
    const uint32_t* mrow0 = &g_mb[(bb * kS + qrow0) * kW];
    const uint32_t* mrow1 = &g_mb[(bb * kS + qrow1) * kW];

    constexpr int NC = kS / 32;   // 64 chunks
    for (int c = 0; c < NC; c++) {
        const int cur = c & 1, nxt = cur ^ 1;
        const bool more = (c + 1 < NC);
        float4 k0n, k1n;
        if (more) {
            const int keyg = (c + 1) * 32 + lane;
            const float* ks = Kp + (size_t)keyg * kHD + kband;
            k0n = *(const float4*)ks;
            k1n = *(const float4*)(ks + 4);
            const uint32_t vdst =
                smem_u32(VsBase + nxt * 32 * 68 + vkey * 68 + vhd);
            const float* vs = Vp + (size_t)((c + 1) * 32 + vkey) * kHD + vhd;
            cp16(vdst, vs);
            cp16(vdst + 16, vs + 4);
            cp_commit();
        }
        const float* Ks = KsBase + cur * 64 * 36;
        const float* Vs = VsBase + cur * 32 * 68;

        // ---- S = Q K^T ----
        float sacc[4][4];
#pragma unroll
        for (int nt = 0; nt < 4; nt++) {
            sacc[nt][0] = 0.f; sacc[nt][1] = 0.f;
            sacc[nt][2] = 0.f; sacc[nt][3] = 0.f;
        }
#pragma unroll
        for (int j = 0; j < 4; j++) {
#pragma unroll
            for (int nt = 0; nt < 4; nt++) {
                uint32_t bhf[2], blf[2];
                split2(Ks[(16 * j + 2 * t) * 36 + nt * 8 + g],
                       Ks[(16 * j + 2 * t + 1) * 36 + nt * 8 + g],
                       bhf[0], blf[0]);
                split2(Ks[(16 * j + 2 * t + 8) * 36 + nt * 8 + g],
                       Ks[(16 * j + 2 * t + 9) * 36 + nt * 8 + g],
                       bhf[1], blf[1]);
                mma_bf16(sacc[nt], qa_h[j], bhf);
                mma_bf16(sacc[nt], qa_h[j], blf);
                mma_bf16(sacc[nt], qa_l[j], bhf);
            }
        }

        // ---- mask + exp -> P (regs), rowsum ----
        const uint32_t w0 = mrow0[c];
        const uint32_t w1 = mrow1[c];
#pragma unroll
        for (int nt = 0; nt < 4; nt++) {
            const int b0 = nt * 8 + 2 * t;
            const float e0 = __expf(sacc[nt][0] * 0.125f);
            const float e1 = __expf(sacc[nt][1] * 0.125f);
            const float e2 = __expf(sacc[nt][2] * 0.125f);
            const float e3 = __expf(sacc[nt][3] * 0.125f);
            sacc[nt][0] = ((w0 >> b0) & 1u)       ? e0 : 0.0f;
            sacc[nt][1] = ((w0 >> (b0 + 1)) & 1u) ? e1 : 0.0f;
            sacc[nt][2] = ((w1 >> b0) & 1u)       ? e2 : 0.0f;
            sacc[nt][3] = ((w1 >> (b0 + 1)) & 1u) ? e3 : 0.0f;
            rs0 += sacc[nt][0] + sacc[nt][1];
            rs1 += sacc[nt][2] + sacc[nt][3];
        }

        // ---- O += P V ----
#pragma unroll
        for (int ks2 = 0; ks2 < 2; ks2++) {
            uint32_t pah[4], pal[4];
            split2(sacc[2 * ks2][0],     sacc[2 * ks2][1],     pah[0], pal[0]);
            split2(sacc[2 * ks2][2],     sacc[2 * ks2][3],     pah[1], pal[1]);
            split2(sacc[2 * ks2 + 1][0], sacc[2 * ks2 + 1][1], pah[2], pal[2]);
            split2(sacc[2 * ks2 + 1][2], sacc[2 * ks2 + 1][3], pah[3], pal[3]);
#pragma unroll
            for (int nt2 = 0; nt2 < 8; nt2++) {
                uint32_t bhf[2], blf[2];
                split2(Vs[(16 * ks2 + 2 * t) * 68 + nt2 * 8 + g],
                       Vs[(16 * ks2 + 2 * t + 1) * 68 + nt2 * 8 + g],
                       bhf[0], blf[0]);
                split2(Vs[(16 * ks2 + 2 * t + 8) * 68 + nt2 * 8 + g],
                       Vs[(16 * ks2 + 2 * t + 9) * 68 + nt2 * 8 + g],
                       bhf[1], blf[1]);
                mma_bf16(oacc[nt2], pah, bhf);
                mma_bf16(oacc[nt2], pah, blf);
                mma_bf16(oacc[nt2], pal, bhf);
            }
        }

        if (more) {
            float* Kn = KsBase + nxt * 64 * 36;
            Kn[(kband + 0) * 36 + lane] = k0n.x;
            Kn[(kband + 1) * 36 + lane] = k0n.y;
            Kn[(kband + 2) * 36 + lane] = k0n.z;
            Kn[(kband + 3) * 36 + lane] = k0n.w;
            Kn[(kband + 4) * 36 + lane] = k1n.x;
            Kn[(kband + 5) * 36 + lane] = k1n.y;
            Kn[(kband + 6) * 36 + lane] = k1n.z;
            Kn[(kband + 7) * 36 + lane] = k1n.w;
            cp_wait0();
            __syncthreads();
        }
    }

    // ---- rowsum butterfly over the quad ----
#pragma unroll
    for (int o = 1; o <= 2; o <<= 1) {
        rs0 += __shfl_xor_sync(0xffffffffu, rs0, o);
        rs1 += __shfl_xor_sync(0xffffffffu, rs1, o);
    }
    const float inv0 = 1.0f / rs0;
    const float inv1 = 1.0f / rs1;

    // ---- epilogue: AO[b, q, h*64 + c] = O / rowsum ----
#pragma unroll
    for (int nt2 = 0; nt2 < 8; nt2++) {
        const int cc = nt2 * 8 + 2 * t;
        *(float2*)&g_ao[((size_t)bb * kS + qrow0) * kD + h * kHD + cc] =
            make_float2(oacc[nt2][0] * inv0, oacc[nt2][1] * inv0);
        *(float2*)&g_ao[((size_t)bb * kS + qrow1) * kD + h * kHD + cc] =
            make_float2(oacc[nt2][2] * inv1, oacc[nt2][3] * inv1);
    }
}

// ---------------------------------------------------------------------------
extern "C" void kernel_launch(void* const* d_in, const int* in_sizes, int n_in,
                              void* d_out, int out_size)
{
    const float* q    = (const float*)d_in[0];
    const float* k    = (const float*)d_in[1];
    const float* v    = (const float*)d_in[2];
    const int*   mask = (const int*)d_in[3];
    const float* wq   = (const float*)d_in[4];
    const float* wk   = (const float*)d_in[5];
    const float* wv   = (const float*)d_in[6];
    const float* wo   = (const float*)d_in[7];
    const float* bo   = (const float*)d_in[8];
    float* out = (float*)d_out;

    const dim3 tb(256);
    maskpack_kernel<<<dim3(kB * kS * kW / (8 * 32)), tb>>>(mask);
    proj_kernel<<<dim3(kM / 128, kD / 128, 3), tb>>>(q, k, v, wq, wk, wv);
    attn_kernel<<<dim3(kS / 128, kBH), tb>>>();
    out_kernel<<<dim3(kM / 128, kD / 128), tb>>>(wo, bo, out);
}